// round 2
// baseline (speedup 1.0000x reference)
#include <cuda_runtime.h>
#include <math_constants.h>

// Problem constants (OnlineTripletLoss: B=8192, D=512)
#define BDIM 8192
#define DDIM 512

// GEMM tiling
#define BM 64
#define BN 64
#define BK 32
#define NSPLIT 4
#define JCHUNK (BDIM / NSPLIT)   // 2048 columns per block

// Scratch (device globals: allocation-free per harness rules)
__device__ __align__(16) float g_An[BDIM * DDIM];
__device__ __align__(16) float g_Pn[BDIM * DDIM];
__device__ float g_diag[BDIM];
__device__ float g_pmin[NSPLIT * BDIM];

// ---------------------------------------------------------------------------
// Kernel 1: row-normalize anchor & positive, compute diag cosine a_n.p_n
// one block per row, 128 threads
// ---------------------------------------------------------------------------
__global__ void normalize_diag_kernel(const float* __restrict__ A,
                                      const float* __restrict__ P) {
    const int row = blockIdx.x;
    const int t = threadIdx.x;           // 128 threads
    const float* a = A + (size_t)row * DDIM;
    const float* p = P + (size_t)row * DDIM;

    float sa = 0.f, sp = 0.f, sap = 0.f;
    #pragma unroll
    for (int k = t; k < DDIM; k += 128) {
        float av = a[k], pv = p[k];
        sa += av * av;
        sp += pv * pv;
        sap += av * pv;
    }
    // warp reduce
    #pragma unroll
    for (int off = 16; off >= 1; off >>= 1) {
        sa  += __shfl_xor_sync(0xffffffff, sa, off);
        sp  += __shfl_xor_sync(0xffffffff, sp, off);
        sap += __shfl_xor_sync(0xffffffff, sap, off);
    }
    __shared__ float red[3][4];
    const int warp = t >> 5, lane = t & 31;
    if (lane == 0) { red[0][warp] = sa; red[1][warp] = sp; red[2][warp] = sap; }
    __syncthreads();
    float tsa  = red[0][0] + red[0][1] + red[0][2] + red[0][3];
    float tsp  = red[1][0] + red[1][1] + red[1][2] + red[1][3];
    float tsap = red[2][0] + red[2][1] + red[2][2] + red[2][3];

    const float inva = rsqrtf(tsa);
    const float invp = rsqrtf(tsp);
    float* an = g_An + (size_t)row * DDIM;
    float* pn = g_Pn + (size_t)row * DDIM;
    #pragma unroll
    for (int k = t; k < DDIM; k += 128) {
        an[k] = a[k] * inva;
        pn[k] = p[k] * invp;
    }
    if (t == 0) g_diag[row] = tsap * inva * invp;
}

// ---------------------------------------------------------------------------
// Kernel 2: fused sim = An @ Pn^T with running row-min over j != i.
// grid: (NSPLIT, BDIM/BM). 256 threads, 16x16 thread grid, 4x4 micro-tile.
// ---------------------------------------------------------------------------
__global__ __launch_bounds__(256, 4)
void gemm_min_kernel() {
    __shared__ float As[BK][BM + 4];
    __shared__ float Ps[BK][BN + 4];

    const int tid = threadIdx.x;
    const int tr = tid >> 4;     // 0..15 -> rows tr*4 .. tr*4+3
    const int tc = tid & 15;     // 0..15 -> cols tc*4 .. tc*4+3
    const int iBase = blockIdx.y * BM;
    const int jChunkBase = blockIdx.x * JCHUNK;

    // loader indexing: each thread loads two float4 along k for A and for P
    const int lr = tid >> 3;           // 0..31
    const int lk = (tid & 7) * 4;      // 0,4,...,28

    float rowmin[4] = {CUDART_INF_F, CUDART_INF_F, CUDART_INF_F, CUDART_INF_F};

    for (int jt = 0; jt < JCHUNK; jt += BN) {
        const int jBase = jChunkBase + jt;
        float acc[4][4];
        #pragma unroll
        for (int m = 0; m < 4; m++)
            #pragma unroll
            for (int n = 0; n < 4; n++)
                acc[m][n] = 0.f;

        for (int k0 = 0; k0 < DDIM; k0 += BK) {
            // load A tile (64 x 32) transposed into As[k][r]
            {
                const float4 v0 = *(const float4*)&g_An[(size_t)(iBase + lr) * DDIM + k0 + lk];
                const float4 v1 = *(const float4*)&g_An[(size_t)(iBase + lr + 32) * DDIM + k0 + lk];
                As[lk + 0][lr] = v0.x; As[lk + 1][lr] = v0.y;
                As[lk + 2][lr] = v0.z; As[lk + 3][lr] = v0.w;
                As[lk + 0][lr + 32] = v1.x; As[lk + 1][lr + 32] = v1.y;
                As[lk + 2][lr + 32] = v1.z; As[lk + 3][lr + 32] = v1.w;
            }
            // load P tile (64 x 32) transposed into Ps[k][c]
            {
                const float4 v0 = *(const float4*)&g_Pn[(size_t)(jBase + lr) * DDIM + k0 + lk];
                const float4 v1 = *(const float4*)&g_Pn[(size_t)(jBase + lr + 32) * DDIM + k0 + lk];
                Ps[lk + 0][lr] = v0.x; Ps[lk + 1][lr] = v0.y;
                Ps[lk + 2][lr] = v0.z; Ps[lk + 3][lr] = v0.w;
                Ps[lk + 0][lr + 32] = v1.x; Ps[lk + 1][lr + 32] = v1.y;
                Ps[lk + 2][lr + 32] = v1.z; Ps[lk + 3][lr + 32] = v1.w;
            }
            __syncthreads();

            #pragma unroll
            for (int k = 0; k < BK; k++) {
                const float4 a = *(const float4*)&As[k][tr * 4];
                const float4 p = *(const float4*)&Ps[k][tc * 4];
                acc[0][0] += a.x * p.x; acc[0][1] += a.x * p.y;
                acc[0][2] += a.x * p.z; acc[0][3] += a.x * p.w;
                acc[1][0] += a.y * p.x; acc[1][1] += a.y * p.y;
                acc[1][2] += a.y * p.z; acc[1][3] += a.y * p.w;
                acc[2][0] += a.z * p.x; acc[2][1] += a.z * p.y;
                acc[2][2] += a.z * p.z; acc[2][3] += a.z * p.w;
                acc[3][0] += a.w * p.x; acc[3][1] += a.w * p.y;
                acc[3][2] += a.w * p.z; acc[3][3] += a.w * p.w;
            }
            __syncthreads();
        }

        // update running min, excluding the diagonal entry
        #pragma unroll
        for (int m = 0; m < 4; m++) {
            const int gi = iBase + tr * 4 + m;
            #pragma unroll
            for (int n = 0; n < 4; n++) {
                const int gj = jBase + tc * 4 + n;
                const float v = (gi == gj) ? CUDART_INF_F : acc[m][n];
                rowmin[m] = fminf(rowmin[m], v);
            }
        }
    }

    // reduce min across the 16 tc-threads holding the same rows.
    // tc occupies bits [0:4) of tid => lanes differing in bits 0..3 share rows.
    #pragma unroll
    for (int m = 0; m < 4; m++) {
        float v = rowmin[m];
        #pragma unroll
        for (int off = 8; off >= 1; off >>= 1)
            v = fminf(v, __shfl_xor_sync(0xffffffff, v, off));
        if (tc == 0)
            g_pmin[(size_t)blockIdx.x * BDIM + iBase + tr * 4 + m] = v;
    }
}

// ---------------------------------------------------------------------------
// Kernel 3: combine partial mins, compute mean relu(1 + diag - min)
// single block
// ---------------------------------------------------------------------------
__global__ void final_loss_kernel(float* __restrict__ out) {
    const int t = threadIdx.x;   // 256
    float sum = 0.f;
    for (int i = t; i < BDIM; i += 256) {
        float m = g_pmin[i];
        #pragma unroll
        for (int s = 1; s < NSPLIT; s++)
            m = fminf(m, g_pmin[s * BDIM + i]);
        const float l = 1.0f + g_diag[i] - m;
        sum += (l > 0.f) ? l : 0.f;
    }
    #pragma unroll
    for (int off = 16; off >= 1; off >>= 1)
        sum += __shfl_xor_sync(0xffffffff, sum, off);
    __shared__ float red[8];
    const int warp = t >> 5, lane = t & 31;
    if (lane == 0) red[warp] = sum;
    __syncthreads();
    if (t == 0) {
        float total = 0.f;
        #pragma unroll
        for (int w = 0; w < 8; w++) total += red[w];
        out[0] = total / (float)BDIM;
    }
}

// ---------------------------------------------------------------------------
extern "C" void kernel_launch(void* const* d_in, const int* in_sizes, int n_in,
                              void* d_out, int out_size) {
    const float* anchor   = (const float*)d_in[0];
    const float* positive = (const float*)d_in[1];
    float* out = (float*)d_out;

    normalize_diag_kernel<<<BDIM, 128>>>(anchor, positive);
    dim3 grid(NSPLIT, BDIM / BM);
    gemm_min_kernel<<<grid, 256>>>();
    final_loss_kernel<<<1, 256>>>(out);
}